// round 8
// baseline (speedup 1.0000x reference)
#include <cuda_runtime.h>
#include <cuda_fp16.h>
#include <cstdint>

#define BATCH 32
#define SEQ   1024
#define CIN   384
#define HD    64
#define NROWS (BATCH*SEQ)

// q scaled by H^-0.5 * log2(e): softmax done in exp2 domain
#define QSCALE (0.125f * 1.44269504088896f)

// fp16 q/k/v staging (device globals: allocation-guard safe)
__device__ __half g_qh[NROWS*HD];
__device__ __half g_kh[NROWS*HD];
__device__ __half g_vh[NROWS*HD];

#define SW128(off) ((uint32_t)(off) ^ ((((uint32_t)(off)) >> 3) & 0x70u))

__device__ __forceinline__ uint32_t smem_u32(const void* p) {
    uint32_t a;
    asm("{ .reg .u64 t; cvta.to.shared.u64 t, %1; cvt.u32.u64 %0, t; }" : "=r"(a) : "l"(p));
    return a;
}
__device__ __forceinline__ void ldsm_x4(uint32_t addr, uint32_t* r) {
    asm volatile("ldmatrix.sync.aligned.m8n8.x4.shared.b16 {%0,%1,%2,%3}, [%4];"
        : "=r"(r[0]), "=r"(r[1]), "=r"(r[2]), "=r"(r[3]) : "r"(addr));
}
__device__ __forceinline__ void ldsm_x4_t(uint32_t addr, uint32_t* r) {
    asm volatile("ldmatrix.sync.aligned.m8n8.x4.trans.shared.b16 {%0,%1,%2,%3}, [%4];"
        : "=r"(r[0]), "=r"(r[1]), "=r"(r[2]), "=r"(r[3]) : "r"(addr));
}
__device__ __forceinline__ void mma16816(float* d, const uint32_t* a, uint32_t b0, uint32_t b1) {
    asm volatile(
        "mma.sync.aligned.m16n8k16.row.col.f32.f16.f16.f32 "
        "{%0,%1,%2,%3}, {%4,%5,%6,%7}, {%8,%9}, {%0,%1,%2,%3};"
        : "+f"(d[0]), "+f"(d[1]), "+f"(d[2]), "+f"(d[3])
        : "r"(a[0]), "r"(a[1]), "r"(a[2]), "r"(a[3]), "r"(b0), "r"(b1));
}
__device__ __forceinline__ uint32_t pack_h2(float a, float b) {
    __half2 h = __floats2half2_rn(a, b);
    return *(uint32_t*)&h;
}
#define CP_ASYNC16(dst, src) \
    asm volatile("cp.async.cg.shared.global [%0], [%1], 16;" :: "r"(dst), "l"(src) : "memory")
#define CP_COMMIT() asm volatile("cp.async.commit_group;" ::: "memory")
#define CP_WAIT0()  asm volatile("cp.async.wait_group 0;" ::: "memory")

// ---------------------------------------------------------------------------
// Fused QKV projection with register-prefetch pipeline.
// [128 x 192] = x_tile[128 x 384] @ [Wq*s | Wk | Wv]
// 384 threads = 12 warps (4 m x 3 n); warp column wn owns panel q/k/v.
// For each K-chunk kc: gmem loads of kc+1 are issued before the MMAs of kc.
// Static smem: 16KB (A) + 24KB (B) = 40KB.
// ---------------------------------------------------------------------------
__global__ __launch_bounds__(384) void proj_kernel(
    const float* __restrict__ x,
    const float* __restrict__ Wk,
    const float* __restrict__ Wq,
    const float* __restrict__ Wv)
{
    __shared__ __align__(128) __half As[128 * 64];      // 16KB
    __shared__ __align__(128) __half Bs[3 * 64 * 64];   // 24KB

    const int tid = threadIdx.x, lane = tid & 31, w = tid >> 5;
    const int wm = w & 3, wn = w >> 2;        // wn: 0=q, 1=k, 2=v
    const int m0 = blockIdx.x * 128;
    const uint32_t aAs = smem_u32(As), aBs = smem_u32(Bs) + wn * 8192;

    float2 ar[11];   // A tile: 4096 float2 / 384 threads (last iter partial)
    float2 br[16];   // B tiles: 6144 float2 / 384 threads (exact)

    // --- prefetch helpers (unrolled; indices compile-time) ---
    #define LOAD_A(kc) { \
        _Pragma("unroll") \
        for (int t = 0; t < 11; t++) { \
            int i = tid + 384 * t; \
            if (t < 10 || i < 4096) { \
                int r = i >> 5, c2 = i & 31; \
                ar[t] = *(const float2*)(x + (size_t)(m0 + r) * CIN + (kc) * 64 + 2 * c2); \
            } \
        } }
    #define LOAD_B(kc) { \
        _Pragma("unroll") \
        for (int t = 0; t < 16; t++) { \
            int i = tid + 384 * t; \
            int p = i >> 11, rem = i & 2047; \
            int r = rem >> 5, c2 = rem & 31; \
            const float* W = (p == 0) ? Wq : (p == 1) ? Wk : Wv; \
            br[t] = *(const float2*)(W + (size_t)((kc) * 64 + r) * HD + 2 * c2); \
        } }
    #define STORE_A() { \
        _Pragma("unroll") \
        for (int t = 0; t < 11; t++) { \
            int i = tid + 384 * t; \
            if (t < 10 || i < 4096) { \
                int r = i >> 5, c2 = i & 31; \
                *(__half2*)((char*)As + SW128(r * 128 + c2 * 4)) = \
                    __floats2half2_rn(ar[t].x, ar[t].y); \
            } \
        } }
    #define STORE_B() { \
        _Pragma("unroll") \
        for (int t = 0; t < 16; t++) { \
            int i = tid + 384 * t; \
            int p = i >> 11, rem = i & 2047; \
            int r = rem >> 5, c2 = rem & 31; \
            float sc = (p == 0) ? QSCALE : 1.0f; \
            *(__half2*)((char*)Bs + p * 8192 + SW128(r * 128 + c2 * 4)) = \
                __floats2half2_rn(br[t].x * sc, br[t].y * sc); \
        } }

    float acc[2][8][4] = {};

    LOAD_A(0); LOAD_B(0);

    for (int kc = 0; kc < 6; kc++) {
        if (kc) __syncthreads();     // MMA(kc-1) readers done
        STORE_A(); STORE_B();
        __syncthreads();             // tiles visible
        if (kc < 5) { LOAD_A(kc + 1); LOAD_B(kc + 1); }   // overlaps MMAs below

        #pragma unroll
        for (int ks = 0; ks < 4; ks++) {
            uint32_t a[2][4];
            #pragma unroll
            for (int mf = 0; mf < 2; mf++) {
                int row = 32 * wm + 16 * mf + (lane & 15);
                ldsm_x4(aAs + SW128(row * 128 + 32 * ks + 16 * (lane >> 4)), a[mf]);
            }
            #pragma unroll
            for (int p = 0; p < 4; p++) {
                uint32_t bfr[4];
                int krow = 16 * ks + (lane & 15);
                int ncol = 8 * (2 * p + (lane >> 4));
                ldsm_x4_t(aBs + SW128(krow * 128 + ncol * 2), bfr);
                #pragma unroll
                for (int mf = 0; mf < 2; mf++) {
                    mma16816(acc[mf][2 * p],     a[mf], bfr[0], bfr[1]);
                    mma16816(acc[mf][2 * p + 1], a[mf], bfr[2], bfr[3]);
                }
            }
        }
    }

    __half* dst = (wn == 0) ? g_qh : (wn == 1) ? g_kh : g_vh;
    #pragma unroll
    for (int mf = 0; mf < 2; mf++) {
        int row = m0 + 32 * wm + 16 * mf + (lane >> 2);
        #pragma unroll
        for (int nf = 0; nf < 8; nf++) {
            int c2 = 4 * nf + (lane & 3);
            ((__half2*)dst)[(size_t)row * 32 + c2] =
                __floats2half2_rn(acc[mf][nf][0], acc[mf][nf][1]);
            ((__half2*)dst)[(size_t)(row + 8) * 32 + c2] =
                __floats2half2_rn(acc[mf][nf][2], acc[mf][nf][3]);
        }
    }
    #undef LOAD_A
    #undef LOAD_B
    #undef STORE_A
    #undef STORE_B
}

// ---------------------------------------------------------------------------
// Flash attention: Br=128 (8 warps x 16 rows), Bc=64, cp.async double buffer.
// grid (8, 32) = 256 CTAs; __launch_bounds__(256,2) -> all CTAs co-resident.
// Heavy tiles scheduled first. Static smem = 48KB exactly.
// ---------------------------------------------------------------------------
__global__ __launch_bounds__(256, 2) void attn_kernel(float* __restrict__ out)
{
    __shared__ __align__(128) __half Qs[128 * 64];     // 16KB
    __shared__ __align__(128) __half Ks[2][64 * 64];   // 16KB
    __shared__ __align__(128) __half Vs[2][64 * 64];   // 16KB

    const int tid = threadIdx.x, lane = tid & 31, w = tid >> 5;
    const int b = blockIdx.y;
    const int qt = gridDim.x - 1 - blockIdx.x;         // heavy-first
    const int nkt = 2 * (qt + 1);                      // 64-wide K tiles
    const uint32_t aQs = smem_u32(Qs);
    const uint32_t aK0 = smem_u32(Ks), aV0 = smem_u32(Vs);

    const __half* kbase = g_kh + (size_t)b * SEQ * HD;
    const __half* vbase = g_vh + (size_t)b * SEQ * HD;

    // Load Q tile (128 rows)
    const uint4* qg = (const uint4*)(g_qh + (size_t)(b * SEQ + qt * 128) * HD);
    #pragma unroll
    for (int i = tid; i < 1024; i += 256) {
        int r = i >> 3, cg = i & 7;
        *(uint4*)((char*)Qs + SW128(r * 128 + cg * 16)) = qg[i];
    }

    // Prefetch K/V tile 0 into stage 0
    {
        const uint4* kg = (const uint4*)kbase;
        const uint4* vg = (const uint4*)vbase;
        #pragma unroll
        for (int i = tid; i < 512; i += 256) {
            int r = i >> 3, cg = i & 7;
            uint32_t sw = SW128(r * 128 + cg * 16);
            CP_ASYNC16(aK0 + sw, kg + i);
            CP_ASYNC16(aV0 + sw, vg + i);
        }
        CP_COMMIT();
    }
    __syncthreads();

    // Preload Q fragments (warp rows 16w..16w+15)
    uint32_t qf[4][4];
    #pragma unroll
    for (int ks = 0; ks < 4; ks++) {
        int row = 16 * w + (lane & 15);
        ldsm_x4(aQs + SW128(row * 128 + 32 * ks + 16 * (lane >> 4)), qf[ks]);
    }

    float m[2] = {-1e30f, -1e30f}, l[2] = {0.0f, 0.0f};
    float o[8][4] = {};
    int st = 0;

    for (int kt = 0; kt < nkt; kt++) {
        CP_WAIT0();
        __syncthreads();

        if (kt + 1 < nkt) {
            const uint4* kg = (const uint4*)(kbase + (size_t)(kt + 1) * 64 * HD);
            const uint4* vg = (const uint4*)(vbase + (size_t)(kt + 1) * 64 * HD);
            uint32_t dK = aK0 + (st ^ 1) * 8192, dV = aV0 + (st ^ 1) * 8192;
            #pragma unroll
            for (int i = tid; i < 512; i += 256) {
                int r = i >> 3, cg = i & 7;
                uint32_t sw = SW128(r * 128 + cg * 16);
                CP_ASYNC16(dK + sw, kg + i);
                CP_ASYNC16(dV + sw, vg + i);
            }
            CP_COMMIT();
        }

        const uint32_t aKs = aK0 + st * 8192, aVs = aV0 + st * 8192;

        // S = Q @ K^T
        float sacc[8][4] = {};
        #pragma unroll
        for (int ks = 0; ks < 4; ks++) {
            #pragma unroll
            for (int p = 0; p < 4; p++) {
                uint32_t bf[4];
                int key = 16 * p + 8 * (lane >> 4) + (lane & 7);
                uint32_t off = key * 128 + 32 * ks + 16 * ((lane >> 3) & 1);
                ldsm_x4(aKs + SW128(off), bf);
                mma16816(sacc[2 * p],     qf[ks], bf[0], bf[1]);
                mma16816(sacc[2 * p + 1], qf[ks], bf[2], bf[3]);
            }
        }

        // Causal mask (key tiles at or past the diagonal of this 128-row block)
        const int rA = 16 * w + (lane >> 2);     // local rows rA, rA+8 (0..127)
        if (kt >= 2 * qt) {
            const int koff = (kt - 2 * qt) << 6; // 0 or 64
            #pragma unroll
            for (int nf = 0; nf < 8; nf++) {
                int c = 8 * nf + 2 * (lane & 3) + koff;
                if (c     > rA)     sacc[nf][0] = -1e30f;
                if (c + 1 > rA)     sacc[nf][1] = -1e30f;
                if (c     > rA + 8) sacc[nf][2] = -1e30f;
                if (c + 1 > rA + 8) sacc[nf][3] = -1e30f;
            }
        }

        // Online softmax in exp2 domain (quad of 4 lanes shares a row)
        float mt0 = -1e30f, mt1 = -1e30f;
        #pragma unroll
        for (int nf = 0; nf < 8; nf++) {
            mt0 = fmaxf(mt0, fmaxf(sacc[nf][0], sacc[nf][1]));
            mt1 = fmaxf(mt1, fmaxf(sacc[nf][2], sacc[nf][3]));
        }
        mt0 = fmaxf(mt0, __shfl_xor_sync(0xffffffffu, mt0, 1));
        mt0 = fmaxf(mt0, __shfl_xor_sync(0xffffffffu, mt0, 2));
        mt1 = fmaxf(mt1, __shfl_xor_sync(0xffffffffu, mt1, 1));
        mt1 = fmaxf(mt1, __shfl_xor_sync(0xffffffffu, mt1, 2));

        float mn0 = fmaxf(m[0], mt0), mn1 = fmaxf(m[1], mt1);
        float a0 = exp2f(m[0] - mn0), a1 = exp2f(m[1] - mn1);
        m[0] = mn0; m[1] = mn1;

        float la0 = 0.0f, la1 = 0.0f;
        uint32_t ph[8][2];
        #pragma unroll
        for (int nf = 0; nf < 8; nf++) {
            float e0 = exp2f(sacc[nf][0] - mn0);
            float e1 = exp2f(sacc[nf][1] - mn0);
            float e2 = exp2f(sacc[nf][2] - mn1);
            float e3 = exp2f(sacc[nf][3] - mn1);
            la0 += e0 + e1; la1 += e2 + e3;
            ph[nf][0] = pack_h2(e0, e1);
            ph[nf][1] = pack_h2(e2, e3);
        }
        la0 += __shfl_xor_sync(0xffffffffu, la0, 1);
        la0 += __shfl_xor_sync(0xffffffffu, la0, 2);
        la1 += __shfl_xor_sync(0xffffffffu, la1, 1);
        la1 += __shfl_xor_sync(0xffffffffu, la1, 2);
        l[0] = l[0] * a0 + la0;
        l[1] = l[1] * a1 + la1;

        #pragma unroll
        for (int nf = 0; nf < 8; nf++) {
            o[nf][0] *= a0; o[nf][1] *= a0;
            o[nf][2] *= a1; o[nf][3] *= a1;
        }

        // O += P @ V
        #pragma unroll
        for (int ks = 0; ks < 4; ks++) {
            uint32_t pa[4] = {ph[2 * ks][0], ph[2 * ks][1],
                              ph[2 * ks + 1][0], ph[2 * ks + 1][1]};
            #pragma unroll
            for (int p = 0; p < 4; p++) {
                uint32_t vf[4];
                int krow = 16 * ks + (lane & 15);
                int n0   = 8 * (2 * p + (lane >> 4));
                ldsm_x4_t(aVs + SW128(krow * 128 + n0 * 2), vf);
                mma16816(o[2 * p],     pa, vf[0], vf[1]);
                mma16816(o[2 * p + 1], pa, vf[2], vf[3]);
            }
        }
        st ^= 1;
    }

    // Epilogue: normalize and store fp32
    float inv0 = 1.0f / l[0], inv1 = 1.0f / l[1];
    int rowg = b * SEQ + qt * 128 + 16 * w + (lane >> 2);
    #pragma unroll
    for (int nf = 0; nf < 8; nf++) {
        int c = 8 * nf + 2 * (lane & 3);
        *(float2*)(out + (size_t)rowg * HD + c) =
            make_float2(o[nf][0] * inv0, o[nf][1] * inv0);
        *(float2*)(out + (size_t)(rowg + 8) * HD + c) =
            make_float2(o[nf][2] * inv1, o[nf][3] * inv1);
    }
}

// ---------------------------------------------------------------------------
// Launch
// ---------------------------------------------------------------------------
extern "C" void kernel_launch(void* const* d_in, const int* in_sizes, int n_in,
                              void* d_out, int out_size)
{
    // metadata order: x, Wk, Wq, Wv
    const float* x  = (const float*)d_in[0];
    const float* Wk = (const float*)d_in[1];
    const float* Wq = (const float*)d_in[2];
    const float* Wv = (const float*)d_in[3];
    float* out = (float*)d_out;

    proj_kernel<<<NROWS / 128, 384>>>(x, Wk, Wq, Wv);

    dim3 ga(SEQ / 128, BATCH);
    attn_kernel<<<ga, 256>>>(out);
}

// round 11
// speedup vs baseline: 1.0196x; 1.0196x over previous
#include <cuda_runtime.h>
#include <cuda_fp16.h>
#include <cstdint>

#define BATCH 32
#define SEQ   1024
#define CIN   384
#define HD    64
#define NROWS (BATCH*SEQ)

// q scaled by H^-0.5 * log2(e): softmax done in exp2 domain
#define QSCALE (0.125f * 1.44269504088896f)

// fp16 q/k/v staging (device globals: allocation-guard safe)
__device__ __half g_qh[NROWS*HD];
__device__ __half g_kh[NROWS*HD];
__device__ __half g_vh[NROWS*HD];

#define SW128(off) ((uint32_t)(off) ^ ((((uint32_t)(off)) >> 3) & 0x70u))

__device__ __forceinline__ uint32_t smem_u32(const void* p) {
    uint32_t a;
    asm("{ .reg .u64 t; cvta.to.shared.u64 t, %1; cvt.u32.u64 %0, t; }" : "=r"(a) : "l"(p));
    return a;
}
__device__ __forceinline__ void ldsm_x4(uint32_t addr, uint32_t* r) {
    asm volatile("ldmatrix.sync.aligned.m8n8.x4.shared.b16 {%0,%1,%2,%3}, [%4];"
        : "=r"(r[0]), "=r"(r[1]), "=r"(r[2]), "=r"(r[3]) : "r"(addr));
}
__device__ __forceinline__ void ldsm_x4_t(uint32_t addr, uint32_t* r) {
    asm volatile("ldmatrix.sync.aligned.m8n8.x4.trans.shared.b16 {%0,%1,%2,%3}, [%4];"
        : "=r"(r[0]), "=r"(r[1]), "=r"(r[2]), "=r"(r[3]) : "r"(addr));
}
__device__ __forceinline__ void mma16816(float* d, const uint32_t* a, uint32_t b0, uint32_t b1) {
    asm volatile(
        "mma.sync.aligned.m16n8k16.row.col.f32.f16.f16.f32 "
        "{%0,%1,%2,%3}, {%4,%5,%6,%7}, {%8,%9}, {%0,%1,%2,%3};"
        : "+f"(d[0]), "+f"(d[1]), "+f"(d[2]), "+f"(d[3])
        : "r"(a[0]), "r"(a[1]), "r"(a[2]), "r"(a[3]), "r"(b0), "r"(b1));
}
__device__ __forceinline__ uint32_t pack_h2(float a, float b) {
    __half2 h = __floats2half2_rn(a, b);
    return *(uint32_t*)&h;
}
#define CP_ASYNC16(dst, src) \
    asm volatile("cp.async.cg.shared.global [%0], [%1], 16;" :: "r"(dst), "l"(src) : "memory")
#define CP_COMMIT() asm volatile("cp.async.commit_group;" ::: "memory")
#define CP_WAIT0()  asm volatile("cp.async.wait_group 0;" ::: "memory")

// ---------------------------------------------------------------------------
// Fused QKV projection with register-prefetch pipeline (R8 version, kept).
// [128 x 192] = x_tile[128 x 384] @ [Wq*s | Wk | Wv]
// 384 threads = 12 warps (4 m x 3 n); warp column wn owns panel q/k/v.
// ---------------------------------------------------------------------------
__global__ __launch_bounds__(384) void proj_kernel(
    const float* __restrict__ x,
    const float* __restrict__ Wk,
    const float* __restrict__ Wq,
    const float* __restrict__ Wv)
{
    __shared__ __align__(128) __half As[128 * 64];      // 16KB
    __shared__ __align__(128) __half Bs[3 * 64 * 64];   // 24KB

    const int tid = threadIdx.x, lane = tid & 31, w = tid >> 5;
    const int wm = w & 3, wn = w >> 2;        // wn: 0=q, 1=k, 2=v
    const int m0 = blockIdx.x * 128;
    const uint32_t aAs = smem_u32(As), aBs = smem_u32(Bs) + wn * 8192;

    float2 ar[11];
    float2 br[16];

    #define LOAD_A(kc) { \
        _Pragma("unroll") \
        for (int t = 0; t < 11; t++) { \
            int i = tid + 384 * t; \
            if (t < 10 || i < 4096) { \
                int r = i >> 5, c2 = i & 31; \
                ar[t] = *(const float2*)(x + (size_t)(m0 + r) * CIN + (kc) * 64 + 2 * c2); \
            } \
        } }
    #define LOAD_B(kc) { \
        _Pragma("unroll") \
        for (int t = 0; t < 16; t++) { \
            int i = tid + 384 * t; \
            int p = i >> 11, rem = i & 2047; \
            int r = rem >> 5, c2 = rem & 31; \
            const float* W = (p == 0) ? Wq : (p == 1) ? Wk : Wv; \
            br[t] = *(const float2*)(W + (size_t)((kc) * 64 + r) * HD + 2 * c2); \
        } }
    #define STORE_A() { \
        _Pragma("unroll") \
        for (int t = 0; t < 11; t++) { \
            int i = tid + 384 * t; \
            if (t < 10 || i < 4096) { \
                int r = i >> 5, c2 = i & 31; \
                *(__half2*)((char*)As + SW128(r * 128 + c2 * 4)) = \
                    __floats2half2_rn(ar[t].x, ar[t].y); \
            } \
        } }
    #define STORE_B() { \
        _Pragma("unroll") \
        for (int t = 0; t < 16; t++) { \
            int i = tid + 384 * t; \
            int p = i >> 11, rem = i & 2047; \
            int r = rem >> 5, c2 = rem & 31; \
            float sc = (p == 0) ? QSCALE : 1.0f; \
            *(__half2*)((char*)Bs + p * 8192 + SW128(r * 128 + c2 * 4)) = \
                __floats2half2_rn(br[t].x * sc, br[t].y * sc); \
        } }

    float acc[2][8][4] = {};

    LOAD_A(0); LOAD_B(0);

    for (int kc = 0; kc < 6; kc++) {
        if (kc) __syncthreads();
        STORE_A(); STORE_B();
        __syncthreads();
        if (kc < 5) { LOAD_A(kc + 1); LOAD_B(kc + 1); }

        #pragma unroll
        for (int ks = 0; ks < 4; ks++) {
            uint32_t a[2][4];
            #pragma unroll
            for (int mf = 0; mf < 2; mf++) {
                int row = 32 * wm + 16 * mf + (lane & 15);
                ldsm_x4(aAs + SW128(row * 128 + 32 * ks + 16 * (lane >> 4)), a[mf]);
            }
            #pragma unroll
            for (int p = 0; p < 4; p++) {
                uint32_t bfr[4];
                int krow = 16 * ks + (lane & 15);
                int ncol = 8 * (2 * p + (lane >> 4));
                ldsm_x4_t(aBs + SW128(krow * 128 + ncol * 2), bfr);
                #pragma unroll
                for (int mf = 0; mf < 2; mf++) {
                    mma16816(acc[mf][2 * p],     a[mf], bfr[0], bfr[1]);
                    mma16816(acc[mf][2 * p + 1], a[mf], bfr[2], bfr[3]);
                }
            }
        }
    }

    __half* dst = (wn == 0) ? g_qh : (wn == 1) ? g_kh : g_vh;
    #pragma unroll
    for (int mf = 0; mf < 2; mf++) {
        int row = m0 + 32 * wm + 16 * mf + (lane >> 2);
        #pragma unroll
        for (int nf = 0; nf < 8; nf++) {
            int c2 = 4 * nf + (lane & 3);
            ((__half2*)dst)[(size_t)row * 32 + c2] =
                __floats2half2_rn(acc[mf][nf][0], acc[mf][nf][1]);
            ((__half2*)dst)[(size_t)(row + 8) * 32 + c2] =
                __floats2half2_rn(acc[mf][nf][2], acc[mf][nf][3]);
        }
    }
    #undef LOAD_A
    #undef LOAD_B
    #undef STORE_A
    #undef STORE_B
}

// ---------------------------------------------------------------------------
// Flash attention (R7 config): Br=Bc=64, 128 threads (4 warps x 16 rows),
// cp.async double-buffered K/V, 25KB smem, grid (16, 32), heavy-first order.
// ---------------------------------------------------------------------------
__global__ __launch_bounds__(128) void attn_kernel(float* __restrict__ out)
{
    __shared__ __align__(128) __half Qs[64 * 64];
    __shared__ __align__(128) __half Ks[2][64 * 64];
    __shared__ __align__(128) __half Vs[2][64 * 64];

    const int tid = threadIdx.x, lane = tid & 31, w = tid >> 5;
    const int b = blockIdx.y;
    const int qt = gridDim.x - 1 - blockIdx.x;   // heavy-first
    const uint32_t aQs = smem_u32(Qs);
    const uint32_t aK0 = smem_u32(Ks), aV0 = smem_u32(Vs);

    const __half* kbase = g_kh + (size_t)b * SEQ * HD;
    const __half* vbase = g_vh + (size_t)b * SEQ * HD;

    // Load Q tile
    const uint4* qg = (const uint4*)(g_qh + (size_t)(b * SEQ + qt * 64) * HD);
    #pragma unroll
    for (int i = tid; i < 512; i += 128) {
        int r = i >> 3, cg = i & 7;
        *(uint4*)((char*)Qs + SW128(r * 128 + cg * 16)) = qg[i];
    }

    // Prefetch K/V tile 0 into stage 0
    {
        const uint4* kg = (const uint4*)kbase;
        const uint4* vg = (const uint4*)vbase;
        #pragma unroll
        for (int i = tid; i < 512; i += 128) {
            int r = i >> 3, cg = i & 7;
            uint32_t sw = SW128(r * 128 + cg * 16);
            CP_ASYNC16(aK0 + sw, kg + i);
            CP_ASYNC16(aV0 + sw, vg + i);
        }
        CP_COMMIT();
    }
    __syncthreads();   // Qs visible

    // Preload Q fragments
    uint32_t qf[4][4];
    #pragma unroll
    for (int ks = 0; ks < 4; ks++) {
        int row = 16 * w + (lane & 15);
        ldsm_x4(aQs + SW128(row * 128 + 32 * ks + 16 * (lane >> 4)), qf[ks]);
    }

    float m[2] = {-1e30f, -1e30f}, l[2] = {0.0f, 0.0f};
    float o[8][4] = {};
    int st = 0;

    for (int kt = 0; kt <= qt; kt++) {
        CP_WAIT0();
        __syncthreads();   // tile kt ready; stage st^1 reads finished

        if (kt < qt) {
            const uint4* kg = (const uint4*)(kbase + (size_t)(kt + 1) * 64 * HD);
            const uint4* vg = (const uint4*)(vbase + (size_t)(kt + 1) * 64 * HD);
            uint32_t dK = aK0 + (st ^ 1) * 8192, dV = aV0 + (st ^ 1) * 8192;
            #pragma unroll
            for (int i = tid; i < 512; i += 128) {
                int r = i >> 3, cg = i & 7;
                uint32_t sw = SW128(r * 128 + cg * 16);
                CP_ASYNC16(dK + sw, kg + i);
                CP_ASYNC16(dV + sw, vg + i);
            }
            CP_COMMIT();
        }

        const uint32_t aKs = aK0 + st * 8192, aVs = aV0 + st * 8192;

        // S = Q @ K^T
        float sacc[8][4] = {};
        #pragma unroll
        for (int ks = 0; ks < 4; ks++) {
            #pragma unroll
            for (int p = 0; p < 4; p++) {
                uint32_t bf[4];
                int key = 16 * p + 8 * (lane >> 4) + (lane & 7);
                uint32_t off = key * 128 + 32 * ks + 16 * ((lane >> 3) & 1);
                ldsm_x4(aKs + SW128(off), bf);
                mma16816(sacc[2 * p],     qf[ks], bf[0], bf[1]);
                mma16816(sacc[2 * p + 1], qf[ks], bf[2], bf[3]);
            }
        }

        // Causal mask on the diagonal tile
        const int rA = 16 * w + (lane >> 2);
        if (kt == qt) {
            #pragma unroll
            for (int nf = 0; nf < 8; nf++) {
                int c = 8 * nf + 2 * (lane & 3);
                if (c     > rA)     sacc[nf][0] = -1e30f;
                if (c + 1 > rA)     sacc[nf][1] = -1e30f;
                if (c     > rA + 8) sacc[nf][2] = -1e30f;
                if (c + 1 > rA + 8) sacc[nf][3] = -1e30f;
            }
        }

        // Online softmax in exp2 domain (quad of 4 lanes shares a row)
        float mt0 = -1e30f, mt1 = -1e30f;
        #pragma unroll
        for (int nf = 0; nf < 8; nf++) {
            mt0 = fmaxf(mt0, fmaxf(sacc[nf][0], sacc[nf][1]));
            mt1 = fmaxf(mt1, fmaxf(sacc[nf][2], sacc[nf][3]));
        }
        mt0 = fmaxf(mt0, __shfl_xor_sync(0xffffffffu, mt0, 1));
        mt0 = fmaxf(mt0, __shfl_xor_sync(0xffffffffu, mt0, 2));
        mt1 = fmaxf(mt1, __shfl_xor_sync(0xffffffffu, mt1, 1));
        mt1 = fmaxf(mt1, __shfl_xor_sync(0xffffffffu, mt1, 2));

        float mn0 = fmaxf(m[0], mt0), mn1 = fmaxf(m[1], mt1);
        float a0 = exp2f(m[0] - mn0), a1 = exp2f(m[1] - mn1);
        m[0] = mn0; m[1] = mn1;

        float la0 = 0.0f, la1 = 0.0f;
        uint32_t ph[8][2];
        #pragma unroll
        for (int nf = 0; nf < 8; nf++) {
            float e0 = exp2f(sacc[nf][0] - mn0);
            float e1 = exp2f(sacc[nf][1] - mn0);
            float e2 = exp2f(sacc[nf][2] - mn1);
            float e3 = exp2f(sacc[nf][3] - mn1);
            la0 += e0 + e1; la1 += e2 + e3;
            ph[nf][0] = pack_h2(e0, e1);
            ph[nf][1] = pack_h2(e2, e3);
        }
        la0 += __shfl_xor_sync(0xffffffffu, la0, 1);
        la0 += __shfl_xor_sync(0xffffffffu, la0, 2);
        la1 += __shfl_xor_sync(0xffffffffu, la1, 1);
        la1 += __shfl_xor_sync(0xffffffffu, la1, 2);
        l[0] = l[0] * a0 + la0;
        l[1] = l[1] * a1 + la1;

        #pragma unroll
        for (int nf = 0; nf < 8; nf++) {
            o[nf][0] *= a0; o[nf][1] *= a0;
            o[nf][2] *= a1; o[nf][3] *= a1;
        }

        // O += P @ V
        #pragma unroll
        for (int ks = 0; ks < 4; ks++) {
            uint32_t pa[4] = {ph[2 * ks][0], ph[2 * ks][1],
                              ph[2 * ks + 1][0], ph[2 * ks + 1][1]};
            #pragma unroll
            for (int p = 0; p < 4; p++) {
                uint32_t vf[4];
                int krow = 16 * ks + (lane & 15);
                int n0   = 8 * (2 * p + (lane >> 4));
                ldsm_x4_t(aVs + SW128(krow * 128 + n0 * 2), vf);
                mma16816(o[2 * p],     pa, vf[0], vf[1]);
                mma16816(o[2 * p + 1], pa, vf[2], vf[3]);
            }
        }
        st ^= 1;
    }

    // Epilogue: normalize and store fp32
    float inv0 = 1.0f / l[0], inv1 = 1.0f / l[1];
    int rowg = b * SEQ + qt * 64 + 16 * w + (lane >> 2);
    #pragma unroll
    for (int nf = 0; nf < 8; nf++) {
        int c = 8 * nf + 2 * (lane & 3);
        *(float2*)(out + (size_t)rowg * HD + c) =
            make_float2(o[nf][0] * inv0, o[nf][1] * inv0);
        *(float2*)(out + (size_t)(rowg + 8) * HD + c) =
            make_float2(o[nf][2] * inv1, o[nf][3] * inv1);
    }
}

// ---------------------------------------------------------------------------
// Launch
// ---------------------------------------------------------------------------
extern "C" void kernel_launch(void* const* d_in, const int* in_sizes, int n_in,
                              void* d_out, int out_size)
{
    // metadata order: x, Wk, Wq, Wv
    const float* x  = (const float*)d_in[0];
    const float* Wk = (const float*)d_in[1];
    const float* Wq = (const float*)d_in[2];
    const float* Wv = (const float*)d_in[3];
    float* out = (float*)d_out;

    proj_kernel<<<NROWS / 128, 384>>>(x, Wk, Wq, Wv);

    dim3 ga(SEQ / 64, BATCH);
    attn_kernel<<<ga, 128>>>(out);
}